// round 1
// baseline (speedup 1.0000x reference)
#include <cuda_runtime.h>
#include <cuda_bf16.h>
#include <cstdint>

#define HD 128          // hidden dim (fixed by problem)
#define NWARPS 8        // warps per CTA
#define NTHREADS (NWARPS * 32)

// One CTA per segment. batch[] is sorted ascending, so each segment is a
// contiguous row range of x. Online (flash-style) softmax: single pass over x
// computes running max m, denom d = sum exp(s - m), and numerator
// num = sum exp(s - m) * x, per warp; warps combine in smem.
__global__ void __launch_bounds__(NTHREADS)
gap_online_kernel(const float* __restrict__ x,
                  const int*   __restrict__ batch,
                  const float* __restrict__ W,
                  float*       __restrict__ out,
                  int N)
{
    const int seg  = blockIdx.x;
    const int tid  = threadIdx.x;
    const int w    = tid >> 5;
    const int lane = tid & 31;

    // --- segment bounds via binary search (all threads redundantly; L1/L2 hits) ---
    int lo = 0, hi = N;
    while (lo < hi) { int mid = (lo + hi) >> 1; if (batch[mid] < seg)     lo = mid + 1; else hi = mid; }
    const int start = lo;
    hi = N;
    while (lo < hi) { int mid = (lo + hi) >> 1; if (batch[mid] < seg + 1) lo = mid + 1; else hi = mid; }
    const int end = lo;

    __shared__ float s_num[NWARPS * HD];
    __shared__ float s_m[NWARPS];
    __shared__ float s_d[NWARPS];

    if (start == end) {
        // empty segment: reference gives zeros
        for (int j = tid; j < HD; j += NTHREADS) out[seg * HD + j] = 0.0f;
        return;
    }

    // per-lane slice of W (columns 4*lane .. 4*lane+3)
    const float4 Wv = *reinterpret_cast<const float4*>(W + lane * 4);

    const float NEG_INF = __int_as_float(0xff800000);
    float  m = NEG_INF;
    float  d = 0.0f;
    float4 num = make_float4(0.0f, 0.0f, 0.0f, 0.0f);

    for (int i = start + w; i < end; i += NWARPS) {
        const float4 xv = *reinterpret_cast<const float4*>(x + (long long)i * HD + lane * 4);

        // score = dot(x_row, W); bias cancels in softmax (and b == 0)
        float p = xv.x * Wv.x + xv.y * Wv.y + xv.z * Wv.z + xv.w * Wv.w;
        #pragma unroll
        for (int o = 16; o > 0; o >>= 1) p += __shfl_xor_sync(0xffffffffu, p, o);
        const float s = p;  // uniform across the warp

        // online softmax update
        const float mnew  = fmaxf(m, s);
        const float scale = __expf(m - mnew);   // exp(-inf) = 0 on first row
        const float e     = __expf(s - mnew);
        d     = d * scale + e;
        num.x = num.x * scale + e * xv.x;
        num.y = num.y * scale + e * xv.y;
        num.z = num.z * scale + e * xv.z;
        num.w = num.w * scale + e * xv.w;
        m = mnew;
    }

    // stash per-warp partials
    if (lane == 0) { s_m[w] = m; s_d[w] = d; }
    *reinterpret_cast<float4*>(&s_num[w * HD + lane * 4]) = num;
    __syncthreads();

    // combine across warps (done redundantly by all threads; 8 smem reads each)
    float mstar = NEG_INF;
    #pragma unroll
    for (int k = 0; k < NWARPS; k++) mstar = fmaxf(mstar, s_m[k]);

    float coef[NWARPS];
    float dtot = 0.0f;
    #pragma unroll
    for (int k = 0; k < NWARPS; k++) {
        const float c = (s_d[k] > 0.0f) ? __expf(s_m[k] - mstar) : 0.0f;
        coef[k] = c;
        dtot += c * s_d[k];
    }
    const float inv = 1.0f / (dtot + 1e-16f);

    for (int j = tid; j < HD; j += NTHREADS) {
        float o = 0.0f;
        #pragma unroll
        for (int k = 0; k < NWARPS; k++) o += coef[k] * s_num[k * HD + j];
        out[seg * HD + j] = o * inv;
    }
}

extern "C" void kernel_launch(void* const* d_in, const int* in_sizes, int n_in,
                              void* d_out, int out_size)
{
    const float* x     = (const float*)d_in[0];
    // d_in[1] = edge_index (unused by the forward math)
    const int*   batch = (const int*)d_in[2];
    const float* W     = (const float*)d_in[3];
    // d_in[4] = b (zeros; cancels in the softmax)
    float* out = (float*)d_out;

    const int N = in_sizes[2];       // number of nodes
    const int B = out_size / HD;     // number of segments

    gap_online_kernel<<<B, NTHREADS>>>(x, batch, W, out, N);
}

// round 2
// speedup vs baseline: 1.0324x; 1.0324x over previous
#include <cuda_runtime.h>
#include <cuda_bf16.h>
#include <cstdint>

#define HD 128          // hidden dim (fixed by problem)
#define NWARPS 8        // warps per CTA
#define NTHREADS (NWARPS * 32)

// One CTA per segment (batch[] sorted -> contiguous row ranges).
// Single-pass online softmax; 4-row unroll per warp for MLP=4 and a 4x
// shorter carried softmax chain.
__global__ void __launch_bounds__(NTHREADS)
gap_online_kernel(const float* __restrict__ x,
                  const int*   __restrict__ batch,
                  const float* __restrict__ W,
                  float*       __restrict__ out,
                  int N)
{
    const int seg  = blockIdx.x;
    const int tid  = threadIdx.x;
    const int w    = tid >> 5;
    const int lane = tid & 31;

    // --- segment bounds via binary search ---
    int lo = 0, hi = N;
    while (lo < hi) { int mid = (lo + hi) >> 1; if (batch[mid] < seg)     lo = mid + 1; else hi = mid; }
    const int start = lo;
    hi = N;
    while (lo < hi) { int mid = (lo + hi) >> 1; if (batch[mid] < seg + 1) lo = mid + 1; else hi = mid; }
    const int end = lo;

    __shared__ float s_num[NWARPS * HD];
    __shared__ float s_m[NWARPS];
    __shared__ float s_d[NWARPS];

    if (start == end) {
        for (int j = tid; j < HD; j += NTHREADS) out[seg * HD + j] = 0.0f;
        return;
    }

    const float4 Wv = *reinterpret_cast<const float4*>(W + lane * 4);

    const float NEG_INF = __int_as_float(0xff800000);
    float  m = NEG_INF;
    float  d = 0.0f;
    float4 num = make_float4(0.0f, 0.0f, 0.0f, 0.0f);

    const long long col = (long long)lane * 4;
    const int stride = NWARPS;

    int i = start + w;
    // ---- main loop: 4 rows per iteration (4 loads in flight) ----
    for (; i + 3 * stride < end; i += 4 * stride) {
        const float4 xv0 = __ldcs(reinterpret_cast<const float4*>(x + (long long)(i             ) * HD + col));
        const float4 xv1 = __ldcs(reinterpret_cast<const float4*>(x + (long long)(i +     stride) * HD + col));
        const float4 xv2 = __ldcs(reinterpret_cast<const float4*>(x + (long long)(i + 2 * stride) * HD + col));
        const float4 xv3 = __ldcs(reinterpret_cast<const float4*>(x + (long long)(i + 3 * stride) * HD + col));

        float p0 = xv0.x * Wv.x + xv0.y * Wv.y + xv0.z * Wv.z + xv0.w * Wv.w;
        float p1 = xv1.x * Wv.x + xv1.y * Wv.y + xv1.z * Wv.z + xv1.w * Wv.w;
        float p2 = xv2.x * Wv.x + xv2.y * Wv.y + xv2.z * Wv.z + xv2.w * Wv.w;
        float p3 = xv3.x * Wv.x + xv3.y * Wv.y + xv3.z * Wv.z + xv3.w * Wv.w;
        #pragma unroll
        for (int o = 16; o > 0; o >>= 1) {
            p0 += __shfl_xor_sync(0xffffffffu, p0, o);
            p1 += __shfl_xor_sync(0xffffffffu, p1, o);
            p2 += __shfl_xor_sync(0xffffffffu, p2, o);
            p3 += __shfl_xor_sync(0xffffffffu, p3, o);
        }

        const float smax = fmaxf(fmaxf(p0, p1), fmaxf(p2, p3));
        const float mnew = fmaxf(m, smax);
        const float scale = __expf(m - mnew);     // exp(-inf)=0 on first iter
        const float e0 = __expf(p0 - mnew);
        const float e1 = __expf(p1 - mnew);
        const float e2 = __expf(p2 - mnew);
        const float e3 = __expf(p3 - mnew);

        d = d * scale + (e0 + e1) + (e2 + e3);
        num.x = num.x * scale + e0 * xv0.x + e1 * xv1.x + e2 * xv2.x + e3 * xv3.x;
        num.y = num.y * scale + e0 * xv0.y + e1 * xv1.y + e2 * xv2.y + e3 * xv3.y;
        num.z = num.z * scale + e0 * xv0.z + e1 * xv1.z + e2 * xv2.z + e3 * xv3.z;
        num.w = num.w * scale + e0 * xv0.w + e1 * xv1.w + e2 * xv2.w + e3 * xv3.w;
        m = mnew;
    }

    // ---- remainder: one row at a time ----
    for (; i < end; i += stride) {
        const float4 xv = __ldcs(reinterpret_cast<const float4*>(x + (long long)i * HD + col));
        float p = xv.x * Wv.x + xv.y * Wv.y + xv.z * Wv.z + xv.w * Wv.w;
        #pragma unroll
        for (int o = 16; o > 0; o >>= 1) p += __shfl_xor_sync(0xffffffffu, p, o);

        const float mnew = fmaxf(m, p);
        const float scale = __expf(m - mnew);
        const float e = __expf(p - mnew);
        d = d * scale + e;
        num.x = num.x * scale + e * xv.x;
        num.y = num.y * scale + e * xv.y;
        num.z = num.z * scale + e * xv.z;
        num.w = num.w * scale + e * xv.w;
        m = mnew;
    }

    // stash per-warp partials
    if (lane == 0) { s_m[w] = m; s_d[w] = d; }
    *reinterpret_cast<float4*>(&s_num[w * HD + lane * 4]) = num;
    __syncthreads();

    // combine across warps
    float mstar = NEG_INF;
    #pragma unroll
    for (int k = 0; k < NWARPS; k++) mstar = fmaxf(mstar, s_m[k]);

    float coef[NWARPS];
    float dtot = 0.0f;
    #pragma unroll
    for (int k = 0; k < NWARPS; k++) {
        const float c = (s_d[k] > 0.0f) ? __expf(s_m[k] - mstar) : 0.0f;
        coef[k] = c;
        dtot += c * s_d[k];
    }
    const float inv = 1.0f / (dtot + 1e-16f);

    for (int j = tid; j < HD; j += NTHREADS) {
        float o = 0.0f;
        #pragma unroll
        for (int k = 0; k < NWARPS; k++) o += coef[k] * s_num[k * HD + j];
        out[seg * HD + j] = o * inv;
    }
}

extern "C" void kernel_launch(void* const* d_in, const int* in_sizes, int n_in,
                              void* d_out, int out_size)
{
    const float* x     = (const float*)d_in[0];
    // d_in[1] = edge_index (unused by the forward math)
    const int*   batch = (const int*)d_in[2];
    const float* W     = (const float*)d_in[3];
    // d_in[4] = b (zeros; cancels in the softmax)
    float* out = (float*)d_out;

    const int N = in_sizes[2];       // number of nodes
    const int B = out_size / HD;     // number of segments

    gap_online_kernel<<<B, NTHREADS>>>(x, batch, W, out, N);
}